// round 10
// baseline (speedup 1.0000x reference)
#include <cuda_runtime.h>
#include <math.h>

#define NUM_SPH 7
#define NUM_RAD 6
#define NBASIS  (NUM_SPH * NUM_RAD)   // 42
#define MAX_E   524288

#define TABN    1024                  // lerp intervals; table = 172KB, L1-resident
#define TABROW  44                    // 176B row stride: 16B-aligned float4

#define BT      128                   // triplets per out-block
#define OTPB    224                   // 7 warps; 128*42/4 = 1344 = 6*224
#define NCHUNK  5

// root scan grid: x in [3.0, 34.035]
#define SCAN_NP   6208
#define SCAN_LO   3.0
#define SCAN_H    0.005

// --------------------------------------------------------------------------
__device__ float g_zeros[NUM_SPH][NUM_RAD];
__device__ float g_norms[NUM_SPH][NUM_RAD];
__device__ __align__(256) float g_tab[(size_t)(TABN + 1) * TABROW];  // 180 KB

// --------------------------------------------------------------------------
__device__ __forceinline__ void jn_pair_d(int l, double z, double& f, double& fm) {
    double s = sin(z), c = cos(z);
    double j0 = s / z;
    if (l == 0) { f = j0; fm = c / z; return; }      // j_{-1} = cos/z
    double j1 = s / (z * z) - c / z;
    double a = j0, b = j1;
    for (int i = 1; i < l; ++i) {
        double nx = (2.0 * i + 1.0) / z * b - a;
        a = b; b = nx;
    }
    f = b; fm = a;
}

// --------------------------------------------------------------------------
// 1) fused scan + bracket + Newton: one block per l.
//    - sign-scan j_l (fp32) on the grid into SMEM
//    - prefix-count sign changes -> first 6 brackets
//    - threads 0..5: safeguarded fp64 Newton for roots k=0..5 + norms
// --------------------------------------------------------------------------
__global__ void setup_kernel() {
    __shared__ unsigned char sg[SCAN_NP];
    __shared__ int cnt[256];
    __shared__ int brk[NUM_RAD];
    int l = blockIdx.x;
    int t = threadIdx.x;

    for (int p = t; p < SCAN_NP; p += 256) {
        float x = (float)(SCAN_LO + SCAN_H * (double)p);
        float s, c;
        sincosf(x, &s, &c);
        float j0 = s / x;
        float v = j0;
        if (l > 0) {
            float j1 = s / (x * x) - c / x;
            float a = j0, b = j1;
            for (int i = 1; i < l; ++i) {
                float nx = (2.0f * i + 1.0f) / x * b - a;
                a = b; b = nx;
            }
            v = b;
        }
        sg[p] = (unsigned char)(v < 0.0f);
    }
    __syncthreads();

    const int NI  = SCAN_NP - 1;
    const int per = (NI + 255) / 256;
    int i0 = t * per, i1 = i0 + per; if (i1 > NI) i1 = NI;

    int local = 0;
    for (int i = i0; i < i1; ++i) local += (sg[i] != sg[i + 1]);
    cnt[t] = local;
    __syncthreads();

    if (t == 0) {
        int run = 0;
        for (int j = 0; j < 256; ++j) { int c0 = cnt[j]; cnt[j] = run; run += c0; }
    }
    __syncthreads();

    int r = cnt[t];
    for (int i = i0; i < i1; ++i) {
        if (sg[i] != sg[i + 1]) {
            if (r < NUM_RAD) brk[r] = i;
            ++r;
        }
    }
    __syncthreads();

    if (t < NUM_RAD) {
        int k = t;
        int i = brk[k];
        double lo = SCAN_LO + SCAN_H * (double)i - SCAN_H;
        double hi = lo + 3.0 * SCAN_H;
        double flo, fd;
        jn_pair_d(l, lo, flo, fd);

        double z = 0.5 * (lo + hi);
        for (int it = 0; it < 8; ++it) {
            double f, fm;
            jn_pair_d(l, z, f, fm);
            if ((f < 0.0) == (flo < 0.0)) { lo = z; flo = f; } else { hi = z; }
            double fp = fm - ((double)(l + 1) / z) * f;
            double zn = z - f / fp;
            if (!(zn > lo && zn < hi)) zn = 0.5 * (lo + hi);
            z = zn;
        }

        double f7, fm7;
        jn_pair_d(l + 1, z, f7, fm7);
        g_zeros[l][k] = (float)z;
        g_norms[l][k] = (float)(sqrt(2.0) / fabs(f7));
    }
}

// --------------------------------------------------------------------------
// 2) Table-gen: exact fp32 reference recurrence at TABN+1 grid points.
// --------------------------------------------------------------------------
__global__ void tab_kernel() {
    int gid = blockIdx.x * blockDim.x + threadIdx.x;
    if (gid >= (TABN + 1) * NUM_SPH) return;
    int l = gid % NUM_SPH;
    int p = gid / NUM_SPH;
    float x = 0.1f + (0.9f / TABN) * (float)p;

    float outv[NUM_RAD];
    #pragma unroll
    for (int k = 0; k < NUM_RAD; ++k) {
        float z = x * g_zeros[l][k];
        float s, c;
        sincosf(z, &s, &c);
        float j0 = s / z;
        float res = j0;
        if (l > 0) {
            float j1 = s / (z * z) - c / z;
            float jm = j0, jc = j1;
            for (int i = 1; i < l; ++i) {
                float jn = (2.0f * i + 1.0f) / z * jc - jm;
                jm = jc; jc = jn;
            }
            res = jc;
        }
        outv[k] = g_norms[l][k] * res;
    }

    float* row = g_tab + (size_t)p * TABROW + l * NUM_RAD;   // 8B-aligned
    float2* q = reinterpret_cast<float2*>(row);
    q[0] = make_float2(outv[0], outv[1]);
    q[1] = make_float2(outv[2], outv[3]);
    q[2] = make_float2(outv[4], outv[5]);
}

// --------------------------------------------------------------------------
// 3) FUSED out:
//    1a: gather dist[idx[t]] -> (row, f); Legendre cbf -> SMEM
//    1b: cooperative lerp, COALESCED LDG.128 from the L1-resident table,
//        staged into srbf (scatter handled by the SMEM crossbar, not L1tex)
//    2 : coalesced float4 multiply-stores (evict-first), 704MB stream
// --------------------------------------------------------------------------
__global__ void __launch_bounds__(OTPB) out_kernel(
        const float* __restrict__ dist,
        const float* __restrict__ angle,
        const int*   __restrict__ idx_kj,
        float*       __restrict__ out,
        int blockOff) {
    __shared__ float srbf[BT][TABROW];   // lerped rows (pads 42,43 unused)
    __shared__ float scbf[BT][8];
    __shared__ float sf[BT];
    __shared__ int   sit[BT];            // pre-scaled table row offset

    const float pref[NUM_SPH] = {
        0.28209479177387814f, 0.48860251190291992f, 0.63078313050504009f,
        0.74635266518023080f, 0.84628437532163443f, 0.93560257962738880f,
        1.01710723628205460f
    };

    int blk = blockIdx.x + blockOff;
    int tid = threadIdx.x;
    int t0  = blk * BT;

    // ---- 1a ----
    if (tid < BT) {
        int t = t0 + tid;
        int e = __ldg(&idx_kj[t]);
        float x = __ldg(&dist[e]) * 0.2f;
        float u = (x - 0.1f) * ((float)TABN / 0.9f);
        if (u < 0.0f) u = 0.0f;
        int i = (int)u;
        if (i > TABN - 1) i = TABN - 1;
        sit[tid] = i * TABROW;
        sf[tid]  = u - (float)i;

        float ct = cosf(angle[t]);
        float pm = 1.0f, pc = ct;
        scbf[tid][0] = pref[0] * pm;
        scbf[tid][1] = pref[1] * pc;
        #pragma unroll
        for (int l = 2; l < NUM_SPH; ++l) {
            float pn = ((2.0f * l - 1.0f) * ct * pc - (l - 1.0f) * pm) / (float)l;
            pm = pc; pc = pn;
            scbf[tid][l] = pref[l] * pn;
        }
    }
    __syncthreads();

    // ---- 1b: 128 triplets x 11 float4 = 1408 cooperative lerps (L1-hit) ----
    for (int c = tid; c < BT * 11; c += OTPB) {
        int q = c / 11;
        int w = c - q * 11;              // float4 index 0..10 (44 floats)
        int ro = sit[q];
        float f = sf[q];
        float4 a = __ldg(reinterpret_cast<const float4*>(g_tab + ro) + w);
        float4 b = __ldg(reinterpret_cast<const float4*>(g_tab + ro + TABROW) + w);
        float4 v;
        v.x = a.x + f * (b.x - a.x);
        v.y = a.y + f * (b.y - a.y);
        v.z = a.z + f * (b.z - a.z);
        v.w = a.w + f * (b.w - a.w);
        *reinterpret_cast<float4*>(&srbf[q][4 * w]) = v;
    }
    __syncthreads();

    // ---- 2: coalesced multiply-store ----
    float4* o4 = reinterpret_cast<float4*>(out + (size_t)blk * (BT * NBASIS));

    #pragma unroll
    for (int it = 0; it < 6; ++it) {
        unsigned w  = it * OTPB + tid;          // 0..1343
        unsigned g  = 4u * w;
        unsigned tl = (g * 6242u) >> 18;        // g/42, exact for g<5376
        unsigned j  = g - tl * 42u;             // even, 0..40

        unsigned tl2 = tl, j2 = j + 2u;
        if (j2 == 42u) { j2 = 0u; tl2 = tl + 1u; }

        float2 v01 = *reinterpret_cast<const float2*>(&srbf[tl ][j ]);
        float2 v23 = *reinterpret_cast<const float2*>(&srbf[tl2][j2]);

        float c1 = scbf[tl ][(j  * 171u) >> 10];
        float c2 = scbf[tl2][(j2 * 171u) >> 10];

        float4 v = make_float4(v01.x * c1, v01.y * c1, v23.x * c2, v23.y * c2);
        __stcs(&o4[w], v);
    }
}

// --------------------------------------------------------------------------
extern "C" void kernel_launch(void* const* d_in, const int* in_sizes, int n_in,
                              void* d_out, int out_size) {
    const float* dist  = (const float*)d_in[0];
    const float* angle = (const float*)d_in[1];
    const int*   idx   = (const int*)  d_in[2];
    float*       out   = (float*)      d_out;
    int T = in_sizes[1];

    setup_kernel<<<NUM_SPH, 256>>>();

    int nTab = (TABN + 1) * NUM_SPH;
    tab_kernel<<<(nTab + 255) / 256, 256>>>();

    int nBlk  = T / BT;                       // 32768
    int chunk = (nBlk + NCHUNK - 1) / NCHUNK; // 6554
    for (int c = 0; c < NCHUNK; ++c) {
        int off = c * chunk;
        int nb  = (off + chunk <= nBlk) ? chunk : (nBlk - off);
        if (nb > 0) out_kernel<<<nb, OTPB>>>(dist, angle, idx, out, off);
    }
}

// round 11
// speedup vs baseline: 1.3587x; 1.3587x over previous
#include <cuda_runtime.h>
#include <cuda_fp16.h>
#include <math.h>

#define NUM_SPH 7
#define NUM_RAD 6
#define NBASIS  (NUM_SPH * NUM_RAD)   // 42
#define MAX_E   524288

#define TABN    512                   // lerp intervals over x in [0.1, 1.0]

#define BT      128                   // triplets per out-block
#define OTPB    224                   // 7 warps; 128*42/2 = 2688 = 12*224
#define NCHUNK  4                     // 3 setup launches + 4 outs: ncu idx 5 = out

// root scan grid: x in [3.0, 34.035]
#define SCAN_NP   6208
#define SCAN_LO   3.0
#define SCAN_H    0.005

// --------------------------------------------------------------------------
__device__ float g_zeros[NUM_SPH][NUM_RAD];
__device__ float g_norms[NUM_SPH][NUM_RAD];
__device__ __align__(256) float  g_tabv[(size_t)(TABN + 1) * NBASIS]; // 86 KB fp32 values
__device__ __align__(256) __half g_tabd[(size_t)TABN * NBASIS];       // 43 KB fp16 deltas

// --------------------------------------------------------------------------
__device__ __forceinline__ void jn_pair_d(int l, double z, double& f, double& fm) {
    double s = sin(z), c = cos(z);
    double j0 = s / z;
    if (l == 0) { f = j0; fm = c / z; return; }      // j_{-1} = cos/z
    double j1 = s / (z * z) - c / z;
    double a = j0, b = j1;
    for (int i = 1; i < l; ++i) {
        double nx = (2.0 * i + 1.0) / z * b - a;
        a = b; b = nx;
    }
    f = b; fm = a;
}

// --------------------------------------------------------------------------
// 1) fused scan + bracket + Newton: one block per l.
// --------------------------------------------------------------------------
__global__ void setup_kernel() {
    __shared__ unsigned char sg[SCAN_NP];
    __shared__ int cnt[256];
    __shared__ int brk[NUM_RAD];
    int l = blockIdx.x;
    int t = threadIdx.x;

    for (int p = t; p < SCAN_NP; p += 256) {
        float x = (float)(SCAN_LO + SCAN_H * (double)p);
        float s, c;
        sincosf(x, &s, &c);
        float j0 = s / x;
        float v = j0;
        if (l > 0) {
            float j1 = s / (x * x) - c / x;
            float a = j0, b = j1;
            for (int i = 1; i < l; ++i) {
                float nx = (2.0f * i + 1.0f) / x * b - a;
                a = b; b = nx;
            }
            v = b;
        }
        sg[p] = (unsigned char)(v < 0.0f);
    }
    __syncthreads();

    const int NI  = SCAN_NP - 1;
    const int per = (NI + 255) / 256;
    int i0 = t * per, i1 = i0 + per; if (i1 > NI) i1 = NI;

    int local = 0;
    for (int i = i0; i < i1; ++i) local += (sg[i] != sg[i + 1]);
    cnt[t] = local;
    __syncthreads();

    if (t == 0) {
        int run = 0;
        for (int j = 0; j < 256; ++j) { int c0 = cnt[j]; cnt[j] = run; run += c0; }
    }
    __syncthreads();

    int r = cnt[t];
    for (int i = i0; i < i1; ++i) {
        if (sg[i] != sg[i + 1]) {
            if (r < NUM_RAD) brk[r] = i;
            ++r;
        }
    }
    __syncthreads();

    if (t < NUM_RAD) {
        int k = t;
        int i = brk[k];
        double lo = SCAN_LO + SCAN_H * (double)i - SCAN_H;
        double hi = lo + 3.0 * SCAN_H;
        double flo, fd;
        jn_pair_d(l, lo, flo, fd);

        double z = 0.5 * (lo + hi);
        for (int it = 0; it < 8; ++it) {
            double f, fm;
            jn_pair_d(l, z, f, fm);
            if ((f < 0.0) == (flo < 0.0)) { lo = z; flo = f; } else { hi = z; }
            double fp = fm - ((double)(l + 1) / z) * f;
            double zn = z - f / fp;
            if (!(zn > lo && zn < hi)) zn = 0.5 * (lo + hi);
            z = zn;
        }

        double f7, fm7;
        jn_pair_d(l + 1, z, f7, fm7);
        g_zeros[l][k] = (float)z;
        g_norms[l][k] = (float)(sqrt(2.0) / fabs(f7));
    }
}

// --------------------------------------------------------------------------
// 2) Table-gen: exact fp32 reference recurrence at TABN+1 grid points,
//    compact rows of 42 floats (8B-aligned pairs).
// --------------------------------------------------------------------------
__global__ void tab_kernel() {
    int gid = blockIdx.x * blockDim.x + threadIdx.x;
    if (gid >= (TABN + 1) * NUM_SPH) return;
    int l = gid % NUM_SPH;
    int p = gid / NUM_SPH;
    float x = 0.1f + (0.9f / TABN) * (float)p;

    float outv[NUM_RAD];
    #pragma unroll
    for (int k = 0; k < NUM_RAD; ++k) {
        float z = x * g_zeros[l][k];
        float s, c;
        sincosf(z, &s, &c);
        float j0 = s / z;
        float res = j0;
        if (l > 0) {
            float j1 = s / (z * z) - c / z;
            float jm = j0, jc = j1;
            for (int i = 1; i < l; ++i) {
                float jn = (2.0f * i + 1.0f) / z * jc - jm;
                jm = jc; jc = jn;
            }
            res = jc;
        }
        outv[k] = g_norms[l][k] * res;
    }

    float* row = g_tabv + (size_t)p * NBASIS + l * NUM_RAD;
    float2* q = reinterpret_cast<float2*>(row);
    q[0] = make_float2(outv[0], outv[1]);
    q[1] = make_float2(outv[2], outv[3]);
    q[2] = make_float2(outv[4], outv[5]);
}

// --------------------------------------------------------------------------
// 3) Delta table: d[i][j] = fp16(v[i+1][j] - v[i][j]).
// --------------------------------------------------------------------------
__global__ void delta_kernel() {
    int gid = blockIdx.x * blockDim.x + threadIdx.x;
    if (gid >= TABN * NBASIS) return;
    float d = g_tabv[gid + NBASIS] - g_tabv[gid];
    g_tabd[gid] = __float2half(d);
}

// --------------------------------------------------------------------------
// 4) FUSED out, float2-granularity (no triplet straddle):
//    1a: dist[idx[t]] -> (row offset, f); Legendre cbf -> SMEM
//    2 : 12 iters; per float2 output: 1 LDG.64 (value) + 1 LDG.32 (fp16x2
//        delta), both L1-resident; fma-lerp; STG.64 evict-first.
// --------------------------------------------------------------------------
__global__ void __launch_bounds__(OTPB) out_kernel(
        const float* __restrict__ dist,
        const float* __restrict__ angle,
        const int*   __restrict__ idx_kj,
        float*       __restrict__ out,
        int blockOff) {
    __shared__ float scbf[BT][8];
    __shared__ float2 sif[BT];          // (row offset as int bits, lerp f)

    const float pref[NUM_SPH] = {
        0.28209479177387814f, 0.48860251190291992f, 0.63078313050504009f,
        0.74635266518023080f, 0.84628437532163443f, 0.93560257962738880f,
        1.01710723628205460f
    };

    int blk = blockIdx.x + blockOff;
    int tid = threadIdx.x;
    int t0  = blk * BT;

    // ---- 1a ----
    if (tid < BT) {
        int t = t0 + tid;
        int e = __ldg(&idx_kj[t]);
        float x = __ldg(&dist[e]) * 0.2f;
        float u = (x - 0.1f) * ((float)TABN / 0.9f);
        if (u < 0.0f) u = 0.0f;
        int i = (int)u;
        if (i > TABN - 1) i = TABN - 1;
        sif[tid] = make_float2(__int_as_float(i * NBASIS), u - (float)i);

        float ct = cosf(angle[t]);
        float pm = 1.0f, pc = ct;
        scbf[tid][0] = pref[0] * pm;
        scbf[tid][1] = pref[1] * pc;
        #pragma unroll
        for (int l = 2; l < NUM_SPH; ++l) {
            float pn = ((2.0f * l - 1.0f) * ct * pc - (l - 1.0f) * pm) / (float)l;
            pm = pc; pc = pn;
            scbf[tid][l] = pref[l] * pn;
        }
    }
    __syncthreads();

    // ---- 2 ----
    float2* o2 = reinterpret_cast<float2*>(out + (size_t)blk * (BT * NBASIS));

    #pragma unroll
    for (int it = 0; it < 12; ++it) {
        unsigned w  = it * OTPB + tid;          // 0..2687
        unsigned g  = 2u * w;                   // even
        unsigned tl = (g * 6242u) >> 18;        // g/42, exact for g<5376
        unsigned j  = g - tl * 42u;             // even, 0..40

        float2 rf = sif[tl];
        int    ro = __float_as_int(rf.x);       // i * 42
        float  f  = rf.y;

        float2  v = __ldg(reinterpret_cast<const float2*>(g_tabv + ro + j));
        __half2 dh = __ldg(reinterpret_cast<const __half2*>(g_tabd + ro + j));
        float2  d = __half22float2(dh);

        float c = scbf[tl][(j * 171u) >> 10];   // j/6

        float2 r;
        r.x = (v.x + f * d.x) * c;
        r.y = (v.y + f * d.y) * c;
        __stcs(&o2[w], r);
    }
}

// --------------------------------------------------------------------------
extern "C" void kernel_launch(void* const* d_in, const int* in_sizes, int n_in,
                              void* d_out, int out_size) {
    const float* dist  = (const float*)d_in[0];
    const float* angle = (const float*)d_in[1];
    const int*   idx   = (const int*)  d_in[2];
    float*       out   = (float*)      d_out;
    int T = in_sizes[1];

    setup_kernel<<<NUM_SPH, 256>>>();

    int nTab = (TABN + 1) * NUM_SPH;
    tab_kernel<<<(nTab + 255) / 256, 256>>>();

    int nD = TABN * NBASIS;
    delta_kernel<<<(nD + 255) / 256, 256>>>();

    int nBlk  = T / BT;                       // 32768
    int chunk = (nBlk + NCHUNK - 1) / NCHUNK; // 8192
    for (int c = 0; c < NCHUNK; ++c) {
        int off = c * chunk;
        int nb  = (off + chunk <= nBlk) ? chunk : (nBlk - off);
        if (nb > 0) out_kernel<<<nb, OTPB>>>(dist, angle, idx, out, off);
    }
}

// round 12
// speedup vs baseline: 1.6126x; 1.1868x over previous
#include <cuda_runtime.h>
#include <cuda_fp16.h>
#include <math.h>

#define NUM_SPH 7
#define NUM_RAD 6
#define NBASIS  (NUM_SPH * NUM_RAD)   // 42
#define MAX_E   524288

#define TABN    512                   // lerp intervals over x in [0.1, 1.0]
#define NREC    (NBASIS / 2)          // 21 packed records per row

#define BT      128                   // triplets per out-block
#define OTPB    224                   // 7 warps; 128*42/2 = 2688 = 12*224
#define NCHUNK  4

// root scan grid: x in [3.0, 34.035]
#define SCAN_NP   6208
#define SCAN_LO   3.0
#define SCAN_H    0.005

// --------------------------------------------------------------------------
__device__ float g_zeros[NUM_SPH][NUM_RAD];
__device__ float g_norms[NUM_SPH][NUM_RAD];
// packed record per (row i, even j): half4 = (v_j, v_j+1, d_j, d_j+1), 8B.
// row stride = 21 records = 168B. total = 513*168B = 86KB -> L1-resident.
__device__ __align__(256) uint2 g_tabp[(size_t)(TABN + 1) * NREC];

// --------------------------------------------------------------------------
__device__ __forceinline__ void jn_pair_d(int l, double z, double& f, double& fm) {
    double s = sin(z), c = cos(z);
    double j0 = s / z;
    if (l == 0) { f = j0; fm = c / z; return; }      // j_{-1} = cos/z
    double j1 = s / (z * z) - c / z;
    double a = j0, b = j1;
    for (int i = 1; i < l; ++i) {
        double nx = (2.0 * i + 1.0) / z * b - a;
        a = b; b = nx;
    }
    f = b; fm = a;
}

// --------------------------------------------------------------------------
// 1) fused scan + bracket + Newton: one block per l.
// --------------------------------------------------------------------------
__global__ void setup_kernel() {
    __shared__ unsigned char sg[SCAN_NP];
    __shared__ int cnt[256];
    __shared__ int brk[NUM_RAD];
    int l = blockIdx.x;
    int t = threadIdx.x;

    for (int p = t; p < SCAN_NP; p += 256) {
        float x = (float)(SCAN_LO + SCAN_H * (double)p);
        float s, c;
        sincosf(x, &s, &c);
        float j0 = s / x;
        float v = j0;
        if (l > 0) {
            float j1 = s / (x * x) - c / x;
            float a = j0, b = j1;
            for (int i = 1; i < l; ++i) {
                float nx = (2.0f * i + 1.0f) / x * b - a;
                a = b; b = nx;
            }
            v = b;
        }
        sg[p] = (unsigned char)(v < 0.0f);
    }
    __syncthreads();

    const int NI  = SCAN_NP - 1;
    const int per = (NI + 255) / 256;
    int i0 = t * per, i1 = i0 + per; if (i1 > NI) i1 = NI;

    int local = 0;
    for (int i = i0; i < i1; ++i) local += (sg[i] != sg[i + 1]);
    cnt[t] = local;
    __syncthreads();

    if (t == 0) {
        int run = 0;
        for (int j = 0; j < 256; ++j) { int c0 = cnt[j]; cnt[j] = run; run += c0; }
    }
    __syncthreads();

    int r = cnt[t];
    for (int i = i0; i < i1; ++i) {
        if (sg[i] != sg[i + 1]) {
            if (r < NUM_RAD) brk[r] = i;
            ++r;
        }
    }
    __syncthreads();

    if (t < NUM_RAD) {
        int k = t;
        int i = brk[k];
        double lo = SCAN_LO + SCAN_H * (double)i - SCAN_H;
        double hi = lo + 3.0 * SCAN_H;
        double flo, fd;
        jn_pair_d(l, lo, flo, fd);

        double z = 0.5 * (lo + hi);
        for (int it = 0; it < 5; ++it) {
            double f, fm;
            jn_pair_d(l, z, f, fm);
            if ((f < 0.0) == (flo < 0.0)) { lo = z; flo = f; } else { hi = z; }
            double fp = fm - ((double)(l + 1) / z) * f;
            double zn = z - f / fp;
            if (!(zn > lo && zn < hi)) zn = 0.5 * (lo + hi);
            z = zn;
        }

        double f7, fm7;
        jn_pair_d(l + 1, z, f7, fm7);
        g_zeros[l][k] = (float)z;
        g_norms[l][k] = (float)(sqrt(2.0) / fabs(f7));
    }
}

// --------------------------------------------------------------------------
// helper: fp32 reference recurrence, 6 radial values for (x, l)
// --------------------------------------------------------------------------
__device__ __forceinline__ void rbf_row(float x, int l, float* outv) {
    #pragma unroll
    for (int k = 0; k < NUM_RAD; ++k) {
        float z = x * g_zeros[l][k];
        float s, c;
        sincosf(z, &s, &c);
        float j0 = s / z;
        float res = j0;
        if (l > 0) {
            float j1 = s / (z * z) - c / z;
            float jm = j0, jc = j1;
            for (int i = 1; i < l; ++i) {
                float jn = (2.0f * i + 1.0f) / z * jc - jm;
                jm = jc; jc = jn;
            }
            res = jc;
        }
        outv[k] = g_norms[l][k] * res;
    }
}

// --------------------------------------------------------------------------
// 2) Table-gen: per (grid point p, l) thread computes rbf at x_p and x_{p+1},
//    packs (v, d=v'-v) as half4 records directly. No intermediate fp32 table.
// --------------------------------------------------------------------------
__global__ void tab_kernel() {
    int gid = blockIdx.x * blockDim.x + threadIdx.x;
    if (gid >= (TABN + 1) * NUM_SPH) return;
    int l = gid % NUM_SPH;
    int p = gid / NUM_SPH;
    float x0 = 0.1f + (0.9f / TABN) * (float)p;
    float x1 = 0.1f + (0.9f / TABN) * (float)(p + 1);   // d unused for p==TABN

    float v0[NUM_RAD], v1[NUM_RAD];
    rbf_row(x0, l, v0);
    rbf_row(x1, l, v1);

    uint2* row = g_tabp + (size_t)p * NREC + l * (NUM_RAD / 2);
    #pragma unroll
    for (int r = 0; r < NUM_RAD / 2; ++r) {
        __half2 vh = __floats2half2_rn(v0[2*r], v0[2*r+1]);
        __half2 dh = __floats2half2_rn(v1[2*r] - v0[2*r], v1[2*r+1] - v0[2*r+1]);
        uint2 rec;
        rec.x = *reinterpret_cast<unsigned*>(&vh);
        rec.y = *reinterpret_cast<unsigned*>(&dh);
        row[r] = rec;
    }
}

// --------------------------------------------------------------------------
// 3) FUSED out: per float2 output = 1 scattered LDG.64 (packed half4 record,
//    L1-resident 86KB table) + 1 LDS + 1 dense STG.64 (evict-first).
// --------------------------------------------------------------------------
__global__ void __launch_bounds__(OTPB) out_kernel(
        const float* __restrict__ dist,
        const float* __restrict__ angle,
        const int*   __restrict__ idx_kj,
        float*       __restrict__ out,
        int blockOff) {
    __shared__ float scbf[BT][8];
    __shared__ float2 sif[BT];          // (row record-offset as int bits, lerp f)

    const float pref[NUM_SPH] = {
        0.28209479177387814f, 0.48860251190291992f, 0.63078313050504009f,
        0.74635266518023080f, 0.84628437532163443f, 0.93560257962738880f,
        1.01710723628205460f
    };

    int blk = blockIdx.x + blockOff;
    int tid = threadIdx.x;
    int t0  = blk * BT;

    // ---- 1a ----
    if (tid < BT) {
        int t = t0 + tid;
        int e = __ldg(&idx_kj[t]);
        float x = __ldg(&dist[e]) * 0.2f;
        float u = (x - 0.1f) * ((float)TABN / 0.9f);
        if (u < 0.0f) u = 0.0f;
        int i = (int)u;
        if (i > TABN - 1) i = TABN - 1;
        sif[tid] = make_float2(__int_as_float(i * NREC), u - (float)i);

        float ct = cosf(angle[t]);
        float pm = 1.0f, pc = ct;
        scbf[tid][0] = pref[0] * pm;
        scbf[tid][1] = pref[1] * pc;
        #pragma unroll
        for (int l = 2; l < NUM_SPH; ++l) {
            float pn = ((2.0f * l - 1.0f) * ct * pc - (l - 1.0f) * pm) / (float)l;
            pm = pc; pc = pn;
            scbf[tid][l] = pref[l] * pn;
        }
    }
    __syncthreads();

    // ---- 2 ----
    float2* o2 = reinterpret_cast<float2*>(out + (size_t)blk * (BT * NBASIS));

    #pragma unroll
    for (int it = 0; it < 12; ++it) {
        unsigned w  = it * OTPB + tid;          // 0..2687
        unsigned g  = 2u * w;                   // even
        unsigned tl = (g * 6242u) >> 18;        // g/42, exact for g<5376
        unsigned j  = g - tl * 42u;             // even, 0..40
        unsigned rj = j >> 1;                   // record index within row

        float2 rf = sif[tl];
        int    ro = __float_as_int(rf.x);       // i * NREC
        float  f  = rf.y;

        uint2 rec = __ldg(&g_tabp[ro + rj]);
        float2 v = __half22float2(*reinterpret_cast<__half2*>(&rec.x));
        float2 d = __half22float2(*reinterpret_cast<__half2*>(&rec.y));

        float c = scbf[tl][(j * 171u) >> 10];   // j/6

        float2 r;
        r.x = (v.x + f * d.x) * c;
        r.y = (v.y + f * d.y) * c;
        __stcs(&o2[w], r);
    }
}

// --------------------------------------------------------------------------
extern "C" void kernel_launch(void* const* d_in, const int* in_sizes, int n_in,
                              void* d_out, int out_size) {
    const float* dist  = (const float*)d_in[0];
    const float* angle = (const float*)d_in[1];
    const int*   idx   = (const int*)  d_in[2];
    float*       out   = (float*)      d_out;
    int T = in_sizes[1];

    setup_kernel<<<NUM_SPH, 256>>>();

    int nTab = (TABN + 1) * NUM_SPH;
    tab_kernel<<<(nTab + 255) / 256, 256>>>();

    int nBlk  = T / BT;                       // 32768
    int chunk = (nBlk + NCHUNK - 1) / NCHUNK; // 8192
    for (int c = 0; c < NCHUNK; ++c) {
        int off = c * chunk;
        int nb  = (off + chunk <= nBlk) ? chunk : (nBlk - off);
        if (nb > 0) out_kernel<<<nb, OTPB>>>(dist, angle, idx, out, off);
    }
}